// round 1
// baseline (speedup 1.0000x reference)
#include <cuda_runtime.h>
#include <cstddef>

// Problem constants (fixed by setup_inputs)
#define BQ   2
#define TQ   2048
#define DQ   1024
#define HQ   16
#define HDQ  64
#define ROW3 3072   // 3*DQ

// Scratch (device globals — no allocation allowed)
__device__ float g_qkv[(size_t)BQ * TQ * ROW3];  // [B*T, 3D]; q|k|v, normalized in-place
__device__ float g_att[(size_t)BQ * TQ * DQ];    // attention output in [B,T,D] layout

// ---------------------------------------------------------------------------
// SGEMM:  C[M,N] = A[M,K] @ B[N,K]^T   (both A and B row-major, K contiguous)
// 128x128 tile, BK=8, 256 threads, 8x8 per-thread fragment, prefetched loads.
// Requires M%128==0, N%128==0, K%8==0 (true for all calls here).
// ---------------------------------------------------------------------------
__global__ __launch_bounds__(256) void sgemm_tn(const float* __restrict__ A,
                                                const float* __restrict__ B,
                                                float* __restrict__ C,
                                                int M, int N, int K) {
    __shared__ float As[8][128];
    __shared__ float Bs[8][128];

    const int tid = threadIdx.x;
    const int tx  = tid & 15;   // 0..15 -> output cols (x8)
    const int ty  = tid >> 4;   // 0..15 -> output rows (x8)

    const int row0 = blockIdx.y * 128;
    const int col0 = blockIdx.x * 128;

    // load mapping: each thread loads one float4 of A and one of B per BK step
    const int lr = tid >> 1;          // 0..127 : tile row
    const int lk = (tid & 1) * 4;     // 0 or 4 : k offset

    const float* Ap = A + (size_t)(row0 + lr) * K + lk;
    const float* Bp = B + (size_t)(col0 + lr) * K + lk;

    float acc[8][8];
#pragma unroll
    for (int i = 0; i < 8; i++)
#pragma unroll
        for (int j = 0; j < 8; j++) acc[i][j] = 0.0f;

    float4 a4 = *(const float4*)(Ap);
    float4 b4 = *(const float4*)(Bp);

    for (int k0 = 0; k0 < K; k0 += 8) {
        As[lk + 0][lr] = a4.x; As[lk + 1][lr] = a4.y;
        As[lk + 2][lr] = a4.z; As[lk + 3][lr] = a4.w;
        Bs[lk + 0][lr] = b4.x; Bs[lk + 1][lr] = b4.y;
        Bs[lk + 2][lr] = b4.z; Bs[lk + 3][lr] = b4.w;
        __syncthreads();

        if (k0 + 8 < K) {  // prefetch next tile while computing
            a4 = *(const float4*)(Ap + k0 + 8);
            b4 = *(const float4*)(Bp + k0 + 8);
        }

#pragma unroll
        for (int kk = 0; kk < 8; kk++) {
            float af[8], bf[8];
            *(float4*)&af[0] = *(const float4*)&As[kk][ty * 8];
            *(float4*)&af[4] = *(const float4*)&As[kk][ty * 8 + 4];
            *(float4*)&bf[0] = *(const float4*)&Bs[kk][tx * 8];
            *(float4*)&bf[4] = *(const float4*)&Bs[kk][tx * 8 + 4];
#pragma unroll
            for (int i = 0; i < 8; i++)
#pragma unroll
                for (int j = 0; j < 8; j++)
                    acc[i][j] = fmaf(af[i], bf[j], acc[i][j]);
        }
        __syncthreads();
    }

    float* Cp = C + (size_t)(row0 + ty * 8) * N + col0 + tx * 8;
#pragma unroll
    for (int i = 0; i < 8; i++) {
        *(float4*)(Cp + (size_t)i * N)     = make_float4(acc[i][0], acc[i][1], acc[i][2], acc[i][3]);
        *(float4*)(Cp + (size_t)i * N + 4) = make_float4(acc[i][4], acc[i][5], acc[i][6], acc[i][7]);
    }
}

// ---------------------------------------------------------------------------
// L2-normalize q and k head rows of g_qkv in place. One warp per 64-elem row.
// Total rows: 2(parts) * B*T * H = 131072.
// ---------------------------------------------------------------------------
__global__ __launch_bounds__(256) void normalize_qk(float* __restrict__ qkv) {
    const int gw   = (blockIdx.x * blockDim.x + threadIdx.x) >> 5;
    const int lane = threadIdx.x & 31;
    // gw = part*65536 + bt*16 + h
    const int h    = gw & 15;
    const int bt   = (gw >> 4) & (BQ * TQ - 1);
    const int part = gw >> 16;     // 0 = q, 1 = k

    float* p = qkv + (size_t)bt * ROW3 + part * DQ + h * HDQ;
    float v0 = p[lane];
    float v1 = p[lane + 32];
    float ss = v0 * v0 + v1 * v1;
#pragma unroll
    for (int m = 16; m; m >>= 1) ss += __shfl_xor_sync(0xffffffffu, ss, m);
    const float s = 1.0f / fmaxf(sqrtf(ss), 1e-12f);
    p[lane]      = v0 * s;
    p[lane + 32] = v1 * s;
}

// ---------------------------------------------------------------------------
// Causal yat attention.
// Block = (q-tile of 64, head, batch), 256 threads.
// Per key tile: S = Qn Kn^T (64x64x64), w = S^2 / max(2.01-2S, 1e-6), causal
// mask on diagonal tile, then O += w @ V and den += rowsum(w).
// Q/K smem: float4 rows with XOR swizzle slot = d4 ^ (row & 15).
// S reuses K's smem region (plain layout). Total static smem = 48 KB.
// ---------------------------------------------------------------------------
__global__ __launch_bounds__(256) void yat_attn(const float* __restrict__ qkv,
                                                float* __restrict__ attn) {
    __shared__ float4 sQ [64 * 16];
    __shared__ float4 sKS[64 * 16];   // K (swizzled) in phase A, S (plain) in phase B
    __shared__ float4 sV [64 * 16];   // [s][d], plain

    const int tid = threadIdx.x;
    const int tx  = tid & 15;   // key cols c = tx + 16j ; out dims d = 4*tx..
    const int ty  = tid >> 4;   // query rows r = ty + 16i

    const int qt = blockIdx.x;            // 0..31
    const int h  = blockIdx.y;
    const int b  = blockIdx.z;
    const int q0 = qt * 64;

    const float* qb = qkv + ((size_t)(b * TQ) + q0) * ROW3 + h * HDQ;

    // Load Q tile (swizzled)
#pragma unroll
    for (int it = 0; it < 4; it++) {
        int idx = tid + 256 * it;
        int r = idx >> 4, d4 = idx & 15;
        sQ[r * 16 + (d4 ^ (r & 15))] = *(const float4*)(qb + (size_t)r * ROW3 + d4 * 4);
    }

    float accO[4][4];
    float accD[4];
#pragma unroll
    for (int i = 0; i < 4; i++) {
        accD[i] = 0.0f;
#pragma unroll
        for (int j = 0; j < 4; j++) accO[i][j] = 0.0f;
    }

    const int nt = qt + 1;  // causal: key tiles 0..qt
    for (int kt = 0; kt < nt; kt++) {
        const int s0 = kt * 64;
        const float* kb = qkv + ((size_t)(b * TQ) + s0) * ROW3 + DQ + h * HDQ;
        const float* vb = kb + DQ;

        __syncthreads();  // previous phase B done (and first-iter: Q writes visible)
#pragma unroll
        for (int it = 0; it < 4; it++) {
            int idx = tid + 256 * it;
            int r = idx >> 4, d4 = idx & 15;
            sKS[r * 16 + (d4 ^ (r & 15))] = *(const float4*)(kb + (size_t)r * ROW3 + d4 * 4);
            sV [r * 16 + d4]              = *(const float4*)(vb + (size_t)r * ROW3 + d4 * 4);
        }
        __syncthreads();

        // -------- phase A: S = Qn Kn^T --------
        float S[4][4];
#pragma unroll
        for (int i = 0; i < 4; i++)
#pragma unroll
            for (int j = 0; j < 4; j++) S[i][j] = 0.0f;

#pragma unroll
        for (int d4 = 0; d4 < 16; d4++) {
            float4 a[4], k4[4];
#pragma unroll
            for (int i = 0; i < 4; i++) a[i]  = sQ [(ty + 16 * i) * 16 + (d4 ^ ty)];
#pragma unroll
            for (int j = 0; j < 4; j++) k4[j] = sKS[(tx + 16 * j) * 16 + (d4 ^ tx)];
#pragma unroll
            for (int i = 0; i < 4; i++)
#pragma unroll
                for (int j = 0; j < 4; j++)
                    S[i][j] = fmaf(a[i].x, k4[j].x,
                               fmaf(a[i].y, k4[j].y,
                                fmaf(a[i].z, k4[j].z,
                                 fmaf(a[i].w, k4[j].w, S[i][j]))));
        }
        __syncthreads();  // done reading K region

        // -------- weight transform + causal mask + den partials, S -> smem --------
        const bool diag = (kt == nt - 1);  // on diagonal tile s0 == q0
        float* sS = (float*)sKS;
#pragma unroll
        for (int i = 0; i < 4; i++) {
            const int r = ty + 16 * i;
#pragma unroll
            for (int j = 0; j < 4; j++) {
                const int c = tx + 16 * j;
                const float dv = S[i][j];
                float w = dv * dv * __fdividef(1.0f, fmaxf(2.01f - 2.0f * dv, 1e-6f));
                if (diag && c > r) w = 0.0f;
                accD[i] += w;
                sS[r * 64 + c] = w;
            }
        }
        __syncthreads();

        // -------- phase B: O += w @ V --------
        const float4* sS4 = sKS;
#pragma unroll
        for (int s4 = 0; s4 < 16; s4++) {
            float4 v0 = sV[(s4 * 4 + 0) * 16 + tx];
            float4 v1 = sV[(s4 * 4 + 1) * 16 + tx];
            float4 v2 = sV[(s4 * 4 + 2) * 16 + tx];
            float4 v3 = sV[(s4 * 4 + 3) * 16 + tx];
#pragma unroll
            for (int i = 0; i < 4; i++) {
                float4 si = sS4[(ty + 16 * i) * 16 + s4];
                accO[i][0] = fmaf(si.x, v0.x, fmaf(si.y, v1.x, fmaf(si.z, v2.x, fmaf(si.w, v3.x, accO[i][0]))));
                accO[i][1] = fmaf(si.x, v0.y, fmaf(si.y, v1.y, fmaf(si.z, v2.y, fmaf(si.w, v3.y, accO[i][1]))));
                accO[i][2] = fmaf(si.x, v0.z, fmaf(si.y, v1.z, fmaf(si.z, v2.z, fmaf(si.w, v3.z, accO[i][2]))));
                accO[i][3] = fmaf(si.x, v0.w, fmaf(si.y, v1.w, fmaf(si.z, v2.w, fmaf(si.w, v3.w, accO[i][3]))));
            }
        }
    }

    // Reduce den across the 16 tx-threads sharing each row (contiguous 16-lane group)
#pragma unroll
    for (int i = 0; i < 4; i++) {
        float d = accD[i];
        d += __shfl_xor_sync(0xffffffffu, d, 8);
        d += __shfl_xor_sync(0xffffffffu, d, 4);
        d += __shfl_xor_sync(0xffffffffu, d, 2);
        d += __shfl_xor_sync(0xffffffffu, d, 1);
        accD[i] = d + 1e-6f;
    }

    // Write O / den to [B,T,D] layout (head-merged) for the output GEMM
    float* ob = attn + ((size_t)(b * TQ) + q0) * DQ + h * HDQ + tx * 4;
#pragma unroll
    for (int i = 0; i < 4; i++) {
        const int r = ty + 16 * i;
        const float inv = __fdividef(1.0f, accD[i]);
        *(float4*)(ob + (size_t)r * DQ) =
            make_float4(accO[i][0] * inv, accO[i][1] * inv, accO[i][2] * inv, accO[i][3] * inv);
    }
}

// ---------------------------------------------------------------------------
// kernel_launch
// ---------------------------------------------------------------------------
extern "C" void kernel_launch(void* const* d_in, const int* in_sizes, int n_in,
                              void* d_out, int out_size) {
    (void)in_sizes; (void)n_in; (void)out_size;
    const float* x    = (const float*)d_in[0];   // [B,T,D]
    const float* Wqkv = (const float*)d_in[1];   // [3D, D]
    const float* Wout = (const float*)d_in[2];   // [D, D]
    float* out = (float*)d_out;                  // [B,T,D]

    void* p_qkv_v = nullptr;
    void* p_att_v = nullptr;
    cudaGetSymbolAddress(&p_qkv_v, g_qkv);
    cudaGetSymbolAddress(&p_att_v, g_att);
    float* p_qkv = (float*)p_qkv_v;
    float* p_att = (float*)p_att_v;

    const int M = BQ * TQ;  // 4096

    // 1) qkv = x @ Wqkv^T : [4096,3072]
    sgemm_tn<<<dim3(ROW3 / 128, M / 128), 256>>>(x, Wqkv, p_qkv, M, ROW3, DQ);

    // 2) L2-normalize q,k per head in place (131072 warps)
    normalize_qk<<<(2 * M * HQ) / 8, 256>>>(p_qkv);

    // 3) causal yat attention -> g_att [B,T,D]
    yat_attn<<<dim3(TQ / 64, HQ, BQ), 256>>>(p_qkv, p_att);

    // 4) out = att @ Wout^T : [4096,1024]
    sgemm_tn<<<dim3(DQ / 128, M / 128), 256>>>(p_att, Wout, out, M, DQ, DQ);
}